// round 1
// baseline (speedup 1.0000x reference)
#include <cuda_runtime.h>
#include <cuda_bf16.h>
#include <stdint.h>

#define BATCH 4
#define NSEQ  4096
#define DDIM  1024
#define EDIM  1024

typedef __nv_bfloat16 bf16;

// ---------------- scratch (device globals; no allocations allowed) -------------
__device__ bf16 g_xh[(size_t)BATCH*NSEQ*DDIM], g_xl[(size_t)BATCH*NSEQ*DDIM];
__device__ bf16 g_yh[(size_t)BATCH*NSEQ*DDIM], g_yl[(size_t)BATCH*NSEQ*DDIM];
__device__ bf16 g_wqh[(size_t)EDIM*DDIM], g_wql[(size_t)EDIM*DDIM];
__device__ bf16 g_wkh[(size_t)EDIM*DDIM], g_wkl[(size_t)EDIM*DDIM];
__device__ bf16 g_wvh[(size_t)EDIM*DDIM], g_wvl[(size_t)EDIM*DDIM];
__device__ bf16 g_woh[(size_t)DDIM*EDIM], g_wol[(size_t)DDIM*EDIM];
__device__ bf16 g_qh[(size_t)BATCH*NSEQ*EDIM], g_ql[(size_t)BATCH*NSEQ*EDIM];
__device__ bf16 g_kh[(size_t)BATCH*NSEQ*EDIM], g_kl[(size_t)BATCH*NSEQ*EDIM];
__device__ bf16 g_vh[(size_t)BATCH*NSEQ*EDIM], g_vl[(size_t)BATCH*NSEQ*EDIM];
__device__ float g_S[(size_t)BATCH*NSEQ*NSEQ];
__device__ bf16 g_ph[(size_t)BATCH*NSEQ*NSEQ], g_pl[(size_t)BATCH*NSEQ*NSEQ];
__device__ bf16 g_ch[(size_t)BATCH*NSEQ*EDIM], g_cl[(size_t)BATCH*NSEQ*EDIM];

// ---------------- fp32 -> bf16 hi/lo split ----------------
__global__ void split_kernel(const float4* __restrict__ src,
                             bf16* __restrict__ hi, bf16* __restrict__ lo, int n4)
{
    int i = blockIdx.x * blockDim.x + threadIdx.x;
    if (i >= n4) return;
    float4 v = src[i];
    float vs[4] = {v.x, v.y, v.z, v.w};
    bf16 h[4], l[4];
#pragma unroll
    for (int j = 0; j < 4; j++) {
        h[j] = __float2bfloat16(vs[j]);
        l[j] = __float2bfloat16(vs[j] - __bfloat162float(h[j]));
    }
    __nv_bfloat162 h01; h01.x = h[0]; h01.y = h[1];
    __nv_bfloat162 h23; h23.x = h[2]; h23.y = h[3];
    __nv_bfloat162 l01; l01.x = l[0]; l01.y = l[1];
    __nv_bfloat162 l23; l23.x = l[2]; l23.y = l[3];
    reinterpret_cast<__nv_bfloat162*>(hi)[2*i]   = h01;
    reinterpret_cast<__nv_bfloat162*>(hi)[2*i+1] = h23;
    reinterpret_cast<__nv_bfloat162*>(lo)[2*i]   = l01;
    reinterpret_cast<__nv_bfloat162*>(lo)[2*i+1] = l23;
}

// ---------------- split-bf16 GEMM: C[M,N] = (Ah+Al) @ (Bh+Bl)^T ----------------
// B_NK==1: B stored [N,K] (K contiguous).  B_NK==0: B stored [K,N] (N contiguous).
// OUT_MODE: 0 = fp32 out; 1 = split hi/lo out; 2 = fp32 out + bias.
#define MMA_BF16(c, a, b) \
    asm volatile("mma.sync.aligned.m16n8k16.row.col.f32.bf16.bf16.f32 " \
                 "{%0,%1,%2,%3},{%4,%5,%6,%7},{%8,%9},{%0,%1,%2,%3};\n" \
                 : "+f"(c[0]), "+f"(c[1]), "+f"(c[2]), "+f"(c[3]) \
                 : "r"(a[0]), "r"(a[1]), "r"(a[2]), "r"(a[3]), "r"(b[0]), "r"(b[1]))

template<int B_NK, int OUT_MODE>
__global__ __launch_bounds__(256, 1)
void gemm_split(const bf16* __restrict__ Ah, const bf16* __restrict__ Al,
                const bf16* __restrict__ Bh, const bf16* __restrict__ Bl,
                float* __restrict__ outF, bf16* __restrict__ outHi, bf16* __restrict__ outLo,
                const float* __restrict__ bias,
                int M, int N, int K,
                long long sA, long long sB, long long sC)
{
    __shared__ bf16 As[2][128][40];
    __shared__ bf16 Bs[2][128][40];

    const int z = blockIdx.z;
    Ah += (size_t)z * sA;  Al += (size_t)z * sA;
    Bh += (size_t)z * sB;  Bl += (size_t)z * sB;

    const int tid = threadIdx.x;
    const int m0  = blockIdx.y * 128;
    const int n0  = blockIdx.x * 128;

    // A fill indices (vec8 over [128 rows][32 k]): 512 vecs, 2 per thread
    const int ar0 = tid >> 2,          ak0 = (tid & 3) * 8;
    const int ar1 = (tid + 256) >> 2,  ak1 = ((tid + 256) & 3) * 8;
    // B trans fill indices (vec8 over [32 k][128 n]): k = v>>4, n = (v&15)*8
    const int bk0 = tid >> 4,          bn0 = (tid & 15) * 8;
    const int bk1 = (tid + 256) >> 4,  bn1 = ((tid + 256) & 15) * 8;

    uint4 rAh0, rAh1, rAl0, rAl1, rBh0, rBh1, rBl0, rBl1;

#define LOAD_TILE(kk) do {                                                        \
    rAh0 = *(const uint4*)(Ah + (size_t)(m0 + ar0) * K + (kk) + ak0);             \
    rAh1 = *(const uint4*)(Ah + (size_t)(m0 + ar1) * K + (kk) + ak1);             \
    rAl0 = *(const uint4*)(Al + (size_t)(m0 + ar0) * K + (kk) + ak0);             \
    rAl1 = *(const uint4*)(Al + (size_t)(m0 + ar1) * K + (kk) + ak1);             \
    if (B_NK) {                                                                   \
        rBh0 = *(const uint4*)(Bh + (size_t)(n0 + ar0) * K + (kk) + ak0);         \
        rBh1 = *(const uint4*)(Bh + (size_t)(n0 + ar1) * K + (kk) + ak1);         \
        rBl0 = *(const uint4*)(Bl + (size_t)(n0 + ar0) * K + (kk) + ak0);         \
        rBl1 = *(const uint4*)(Bl + (size_t)(n0 + ar1) * K + (kk) + ak1);         \
    } else {                                                                      \
        rBh0 = *(const uint4*)(Bh + (size_t)((kk) + bk0) * N + n0 + bn0);         \
        rBh1 = *(const uint4*)(Bh + (size_t)((kk) + bk1) * N + n0 + bn1);         \
        rBl0 = *(const uint4*)(Bl + (size_t)((kk) + bk0) * N + n0 + bn0);         \
        rBl1 = *(const uint4*)(Bl + (size_t)((kk) + bk1) * N + n0 + bn1);         \
    } } while (0)

#define STORE_TILE() do {                                                         \
    *(uint4*)&As[0][ar0][ak0] = rAh0;  *(uint4*)&As[0][ar1][ak1] = rAh1;          \
    *(uint4*)&As[1][ar0][ak0] = rAl0;  *(uint4*)&As[1][ar1][ak1] = rAl1;          \
    if (B_NK) {                                                                   \
        *(uint4*)&Bs[0][ar0][ak0] = rBh0;  *(uint4*)&Bs[0][ar1][ak1] = rBh1;      \
        *(uint4*)&Bs[1][ar0][ak0] = rBl0;  *(uint4*)&Bs[1][ar1][ak1] = rBl1;      \
    } else {                                                                      \
        bf16 t[8];                                                                \
        *(uint4*)t = rBh0; _Pragma("unroll") for (int i_ = 0; i_ < 8; i_++) Bs[0][bn0 + i_][bk0] = t[i_]; \
        *(uint4*)t = rBh1; _Pragma("unroll") for (int i_ = 0; i_ < 8; i_++) Bs[0][bn1 + i_][bk1] = t[i_]; \
        *(uint4*)t = rBl0; _Pragma("unroll") for (int i_ = 0; i_ < 8; i_++) Bs[1][bn0 + i_][bk0] = t[i_]; \
        *(uint4*)t = rBl1; _Pragma("unroll") for (int i_ = 0; i_ < 8; i_++) Bs[1][bn1 + i_][bk1] = t[i_]; \
    } } while (0)

    float acc[4][4][4];
#pragma unroll
    for (int t = 0; t < 4; t++)
#pragma unroll
        for (int u = 0; u < 4; u++)
#pragma unroll
            for (int e = 0; e < 4; e++) acc[t][u][e] = 0.0f;

    const int lane = tid & 31;
    const int warp = tid >> 5;
    const int wm0 = (warp & 1) * 64;
    const int wn0 = (warp >> 1) * 32;
    const int arow = lane & 15;
    const int acol = (lane >> 4) * 8;
    const int brow = lane & 7;
    const int bcol = ((lane >> 3) & 1) * 8;

    const int nk = K >> 5;
    LOAD_TILE(0);
    STORE_TILE();
    __syncthreads();

    for (int kt = 0; kt < nk; kt++) {
        if (kt + 1 < nk) LOAD_TILE((kt + 1) << 5);

#pragma unroll
        for (int ks = 0; ks < 2; ks++) {
            const int kb = ks * 16;
            uint32_t ah[4][4], al[4][4], bh[4][2], bl[4][2];
#pragma unroll
            for (int t = 0; t < 4; t++) {
                uint32_t ad = (uint32_t)__cvta_generic_to_shared(&As[0][wm0 + t*16 + arow][kb + acol]);
                asm volatile("ldmatrix.sync.aligned.m8n8.x4.shared.b16 {%0,%1,%2,%3}, [%4];\n"
                             : "=r"(ah[t][0]), "=r"(ah[t][1]), "=r"(ah[t][2]), "=r"(ah[t][3]) : "r"(ad));
                ad = (uint32_t)__cvta_generic_to_shared(&As[1][wm0 + t*16 + arow][kb + acol]);
                asm volatile("ldmatrix.sync.aligned.m8n8.x4.shared.b16 {%0,%1,%2,%3}, [%4];\n"
                             : "=r"(al[t][0]), "=r"(al[t][1]), "=r"(al[t][2]), "=r"(al[t][3]) : "r"(ad));
            }
#pragma unroll
            for (int u = 0; u < 4; u++) {
                uint32_t bd = (uint32_t)__cvta_generic_to_shared(&Bs[0][wn0 + u*8 + brow][kb + bcol]);
                asm volatile("ldmatrix.sync.aligned.m8n8.x2.shared.b16 {%0,%1}, [%2];\n"
                             : "=r"(bh[u][0]), "=r"(bh[u][1]) : "r"(bd));
                bd = (uint32_t)__cvta_generic_to_shared(&Bs[1][wn0 + u*8 + brow][kb + bcol]);
                asm volatile("ldmatrix.sync.aligned.m8n8.x2.shared.b16 {%0,%1}, [%2];\n"
                             : "=r"(bl[u][0]), "=r"(bl[u][1]) : "r"(bd));
            }
#pragma unroll
            for (int t = 0; t < 4; t++)
#pragma unroll
                for (int u = 0; u < 4; u++) {
                    MMA_BF16(acc[t][u], ah[t], bh[u]);   // hi*hi
                    MMA_BF16(acc[t][u], ah[t], bl[u]);   // hi*lo
                    MMA_BF16(acc[t][u], al[t], bh[u]);   // lo*hi
                }
        }
        __syncthreads();
        if (kt + 1 < nk) { STORE_TILE(); __syncthreads(); }
    }

    // epilogue
    const size_t cbase = (size_t)z * sC;
#pragma unroll
    for (int t = 0; t < 4; t++)
#pragma unroll
        for (int u = 0; u < 4; u++) {
            int gm = m0 + wm0 + t * 16 + (lane >> 2);
            int gn = n0 + wn0 + u * 8 + (lane & 3) * 2;
            float v00 = acc[t][u][0], v01 = acc[t][u][1];
            float v10 = acc[t][u][2], v11 = acc[t][u][3];
            if (OUT_MODE == 2) {
                float b0 = bias[gn], b1 = bias[gn + 1];
                v00 += b0; v01 += b1; v10 += b0; v11 += b1;
            }
            if (OUT_MODE == 0 || OUT_MODE == 2) {
                float2 r0 = make_float2(v00, v01);
                float2 r1 = make_float2(v10, v11);
                *(float2*)(outF + cbase + (size_t)gm * N + gn) = r0;
                *(float2*)(outF + cbase + (size_t)(gm + 8) * N + gn) = r1;
            } else {
                bf16 h00 = __float2bfloat16(v00), h01 = __float2bfloat16(v01);
                bf16 h10 = __float2bfloat16(v10), h11 = __float2bfloat16(v11);
                __nv_bfloat162 hp0; hp0.x = h00; hp0.y = h01;
                __nv_bfloat162 hp1; hp1.x = h10; hp1.y = h11;
                __nv_bfloat162 lp0; lp0.x = __float2bfloat16(v00 - __bfloat162float(h00));
                                    lp0.y = __float2bfloat16(v01 - __bfloat162float(h01));
                __nv_bfloat162 lp1; lp1.x = __float2bfloat16(v10 - __bfloat162float(h10));
                                    lp1.y = __float2bfloat16(v11 - __bfloat162float(h11));
                *(__nv_bfloat162*)(outHi + cbase + (size_t)gm * N + gn) = hp0;
                *(__nv_bfloat162*)(outHi + cbase + (size_t)(gm + 8) * N + gn) = hp1;
                *(__nv_bfloat162*)(outLo + cbase + (size_t)gm * N + gn) = lp0;
                *(__nv_bfloat162*)(outLo + cbase + (size_t)(gm + 8) * N + gn) = lp1;
            }
        }
#undef LOAD_TILE
#undef STORE_TILE
}

// ---------------- row softmax (scaled) with split-bf16 output ----------------
__global__ __launch_bounds__(256)
void softmax_split(const float* __restrict__ S, bf16* __restrict__ Ph, bf16* __restrict__ Pl,
                   float scale)
{
    __shared__ float buf[NSEQ];
    __shared__ float red[8];
    const size_t base = (size_t)blockIdx.x * NSEQ;
    const int tid = threadIdx.x;

    float lmax = -1e30f;
#pragma unroll
    for (int i = 0; i < NSEQ / (256 * 4); i++) {
        int idx = (i * 256 + tid) * 4;
        float4 v = *(const float4*)(S + base + idx);
        buf[idx] = v.x; buf[idx + 1] = v.y; buf[idx + 2] = v.z; buf[idx + 3] = v.w;
        lmax = fmaxf(lmax, fmaxf(fmaxf(v.x, v.y), fmaxf(v.z, v.w)));
    }
#pragma unroll
    for (int o = 16; o; o >>= 1) lmax = fmaxf(lmax, __shfl_xor_sync(0xffffffffu, lmax, o));
    if ((tid & 31) == 0) red[tid >> 5] = lmax;
    __syncthreads();
    float rmax = red[0];
#pragma unroll
    for (int j = 1; j < 8; j++) rmax = fmaxf(rmax, red[j]);
    __syncthreads();

    float lsum = 0.0f;
#pragma unroll
    for (int i = 0; i < NSEQ / (256 * 4); i++) {
        int idx = (i * 256 + tid) * 4;
#pragma unroll
        for (int j = 0; j < 4; j++) {
            float e = expf(scale * (buf[idx + j] - rmax));
            buf[idx + j] = e;
            lsum += e;
        }
    }
#pragma unroll
    for (int o = 16; o; o >>= 1) lsum += __shfl_xor_sync(0xffffffffu, lsum, o);
    if ((tid & 31) == 0) red[tid >> 5] = lsum;
    __syncthreads();
    float rsum = red[0];
#pragma unroll
    for (int j = 1; j < 8; j++) rsum += red[j];
    float rinv = 1.0f / rsum;

#pragma unroll
    for (int i = 0; i < NSEQ / (256 * 4); i++) {
        int idx = (i * 256 + tid) * 4;
        bf16 h[4], l[4];
#pragma unroll
        for (int j = 0; j < 4; j++) {
            float p = buf[idx + j] * rinv;
            h[j] = __float2bfloat16(p);
            l[j] = __float2bfloat16(p - __bfloat162float(h[j]));
        }
        __nv_bfloat162 h01; h01.x = h[0]; h01.y = h[1];
        __nv_bfloat162 h23; h23.x = h[2]; h23.y = h[3];
        __nv_bfloat162 l01; l01.x = l[0]; l01.y = l[1];
        __nv_bfloat162 l23; l23.x = l[2]; l23.y = l[3];
        *(__nv_bfloat162*)(Ph + base + idx)     = h01;
        *(__nv_bfloat162*)(Ph + base + idx + 2) = h23;
        *(__nv_bfloat162*)(Pl + base + idx)     = l01;
        *(__nv_bfloat162*)(Pl + base + idx + 2) = l23;
    }
}

// ---------------- host ----------------
extern "C" void kernel_launch(void* const* d_in, const int* in_sizes, int n_in,
                              void* d_out, int out_size)
{
    const float* x  = (const float*)d_in[0];
    const float* y  = (const float*)d_in[1];
    const float* Wq = (const float*)d_in[2];
    const float* Wk = (const float*)d_in[3];
    const float* Wv = (const float*)d_in[4];
    const float* Wo = (const float*)d_in[5];
    const float* bo = (const float*)d_in[6];
    float* out = (float*)d_out;

    void *xh, *xl, *yh, *yl;
    void *wqh, *wql, *wkh, *wkl, *wvh, *wvl, *woh, *wol;
    void *qh, *ql, *kh, *kl, *vh, *vl, *sS, *ph, *pl, *ch, *cl;
    cudaGetSymbolAddress(&xh, g_xh);   cudaGetSymbolAddress(&xl, g_xl);
    cudaGetSymbolAddress(&yh, g_yh);   cudaGetSymbolAddress(&yl, g_yl);
    cudaGetSymbolAddress(&wqh, g_wqh); cudaGetSymbolAddress(&wql, g_wql);
    cudaGetSymbolAddress(&wkh, g_wkh); cudaGetSymbolAddress(&wkl, g_wkl);
    cudaGetSymbolAddress(&wvh, g_wvh); cudaGetSymbolAddress(&wvl, g_wvl);
    cudaGetSymbolAddress(&woh, g_woh); cudaGetSymbolAddress(&wol, g_wol);
    cudaGetSymbolAddress(&qh, g_qh);   cudaGetSymbolAddress(&ql, g_ql);
    cudaGetSymbolAddress(&kh, g_kh);   cudaGetSymbolAddress(&kl, g_kl);
    cudaGetSymbolAddress(&vh, g_vh);   cudaGetSymbolAddress(&vl, g_vl);
    cudaGetSymbolAddress(&sS, g_S);
    cudaGetSymbolAddress(&ph, g_ph);   cudaGetSymbolAddress(&pl, g_pl);
    cudaGetSymbolAddress(&ch, g_ch);   cudaGetSymbolAddress(&cl, g_cl);

    const int MBN = BATCH * NSEQ;            // 16384

    // 1) splits
    {
        int n4 = BATCH * NSEQ * DDIM / 4;    // 4,194,304
        split_kernel<<<n4 / 256, 256>>>((const float4*)x, (bf16*)xh, (bf16*)xl, n4);
        split_kernel<<<n4 / 256, 256>>>((const float4*)y, (bf16*)yh, (bf16*)yl, n4);
        int w4 = EDIM * DDIM / 4;            // 262,144
        split_kernel<<<w4 / 256, 256>>>((const float4*)Wq, (bf16*)wqh, (bf16*)wql, w4);
        split_kernel<<<w4 / 256, 256>>>((const float4*)Wk, (bf16*)wkh, (bf16*)wkl, w4);
        split_kernel<<<w4 / 256, 256>>>((const float4*)Wv, (bf16*)wvh, (bf16*)wvl, w4);
        split_kernel<<<w4 / 256, 256>>>((const float4*)Wo, (bf16*)woh, (bf16*)wol, w4);
    }

    dim3 blk(256);

    // 2) projections: q = y @ Wq^T, k = x @ Wk^T, v = x @ Wv^T   (M=16384, N=1024, K=1024)
    {
        dim3 grid(EDIM / 128, MBN / 128, 1);
        gemm_split<1, 1><<<grid, blk>>>((bf16*)yh, (bf16*)yl, (bf16*)wqh, (bf16*)wql,
                                        nullptr, (bf16*)qh, (bf16*)ql, nullptr,
                                        MBN, EDIM, DDIM, 0, 0, 0);
        gemm_split<1, 1><<<grid, blk>>>((bf16*)xh, (bf16*)xl, (bf16*)wkh, (bf16*)wkl,
                                        nullptr, (bf16*)kh, (bf16*)kl, nullptr,
                                        MBN, EDIM, DDIM, 0, 0, 0);
        gemm_split<1, 1><<<grid, blk>>>((bf16*)xh, (bf16*)xl, (bf16*)wvh, (bf16*)wvl,
                                        nullptr, (bf16*)vh, (bf16*)vl, nullptr,
                                        MBN, EDIM, DDIM, 0, 0, 0);
    }

    // 3) scores: S[b] = q[b] @ k[b]^T   (M=N=4096, K=1024, z=4)
    {
        dim3 grid(NSEQ / 128, NSEQ / 128, BATCH);
        gemm_split<1, 0><<<grid, blk>>>((bf16*)qh, (bf16*)ql, (bf16*)kh, (bf16*)kl,
                                        (float*)sS, nullptr, nullptr, nullptr,
                                        NSEQ, NSEQ, EDIM,
                                        (long long)NSEQ * EDIM, (long long)NSEQ * EDIM,
                                        (long long)NSEQ * NSEQ);
    }

    // 4) softmax rows (scale = 1/sqrt(1024) = 1/32), split output
    softmax_split<<<BATCH * NSEQ, 256>>>((const float*)sS, (bf16*)ph, (bf16*)pl, 1.0f / 32.0f);

    // 5) ctx: C[b] = P[b] @ V[b]   (M=4096, N=1024, K=4096; B is [K,N], z=4)
    {
        dim3 grid(EDIM / 128, NSEQ / 128, BATCH);
        gemm_split<0, 1><<<grid, blk>>>((bf16*)ph, (bf16*)pl, (bf16*)vh, (bf16*)vl,
                                        nullptr, (bf16*)ch, (bf16*)cl, nullptr,
                                        NSEQ, EDIM, NSEQ,
                                        (long long)NSEQ * NSEQ, (long long)NSEQ * EDIM,
                                        (long long)NSEQ * EDIM);
    }

    // 6) out = ctx @ Wo^T + bo   (M=16384, N=1024, K=1024)
    {
        dim3 grid(DDIM / 128, MBN / 128, 1);
        gemm_split<1, 2><<<grid, blk>>>((bf16*)ch, (bf16*)cl, (bf16*)woh, (bf16*)wol,
                                        out, nullptr, nullptr, bo,
                                        MBN, DDIM, EDIM, 0, 0, 0);
    }

    (void)in_sizes; (void)n_in; (void)out_size;
}

// round 3
// speedup vs baseline: 1.4021x; 1.4021x over previous
#include <cuda_runtime.h>
#include <cuda_bf16.h>
#include <stdint.h>

#define BATCH 4
#define NSEQ  4096
#define DDIM  1024
#define EDIM  1024

typedef __nv_bfloat16 bf16;

// ---------------- scratch (device globals; no allocations allowed) -------------
__device__ bf16 g_xh[(size_t)BATCH*NSEQ*DDIM], g_xl[(size_t)BATCH*NSEQ*DDIM];
__device__ bf16 g_yh[(size_t)BATCH*NSEQ*DDIM], g_yl[(size_t)BATCH*NSEQ*DDIM];
__device__ bf16 g_wqh[(size_t)EDIM*DDIM], g_wql[(size_t)EDIM*DDIM];
__device__ bf16 g_wkh[(size_t)EDIM*DDIM], g_wkl[(size_t)EDIM*DDIM];
__device__ bf16 g_wvh[(size_t)EDIM*DDIM], g_wvl[(size_t)EDIM*DDIM];
__device__ bf16 g_woh[(size_t)DDIM*EDIM], g_wol[(size_t)DDIM*EDIM];
__device__ bf16 g_qh[(size_t)BATCH*NSEQ*EDIM], g_ql[(size_t)BATCH*NSEQ*EDIM];
__device__ bf16 g_kh[(size_t)BATCH*NSEQ*EDIM], g_kl[(size_t)BATCH*NSEQ*EDIM];
__device__ bf16 g_vh[(size_t)BATCH*NSEQ*EDIM], g_vl[(size_t)BATCH*NSEQ*EDIM];
__device__ bf16 g_vth[(size_t)BATCH*EDIM*NSEQ], g_vtl[(size_t)BATCH*EDIM*NSEQ];
__device__ float g_S[(size_t)BATCH*NSEQ*NSEQ];
__device__ bf16 g_ph[(size_t)BATCH*NSEQ*NSEQ], g_pl[(size_t)BATCH*NSEQ*NSEQ];
__device__ bf16 g_ch[(size_t)BATCH*NSEQ*EDIM], g_cl[(size_t)BATCH*NSEQ*EDIM];

// ---------------- helpers ----------------
__device__ __forceinline__ uint32_t smem_u32(const void* p) {
    uint32_t a;
    asm("{ .reg .u64 t; cvta.to.shared.u64 t, %1; cvt.u32.u64 %0, t; }" : "=r"(a) : "l"(p));
    return a;
}
__device__ __forceinline__ void cpa16(uint32_t dst, const void* src) {
    asm volatile("cp.async.cg.shared.global [%0], [%1], 16;" :: "r"(dst), "l"(src));
}

#define MMA_BF16(c, a, b) \
    asm volatile("mma.sync.aligned.m16n8k16.row.col.f32.bf16.bf16.f32 " \
                 "{%0,%1,%2,%3},{%4,%5,%6,%7},{%8,%9},{%0,%1,%2,%3};\n" \
                 : "+f"(c[0]), "+f"(c[1]), "+f"(c[2]), "+f"(c[3]) \
                 : "r"(a[0]), "r"(a[1]), "r"(a[2]), "r"(a[3]), "r"(b[0]), "r"(b[1]))

// ---------------- fp32 -> bf16 hi/lo split ----------------
__global__ void split_kernel(const float4* __restrict__ src,
                             bf16* __restrict__ hi, bf16* __restrict__ lo, int n4)
{
    int i = blockIdx.x * blockDim.x + threadIdx.x;
    if (i >= n4) return;
    float4 v = src[i];
    float vs[4] = {v.x, v.y, v.z, v.w};
    bf16 h[4], l[4];
#pragma unroll
    for (int j = 0; j < 4; j++) {
        h[j] = __float2bfloat16(vs[j]);
        l[j] = __float2bfloat16(vs[j] - __bfloat162float(h[j]));
    }
    __nv_bfloat162 h01; h01.x = h[0]; h01.y = h[1];
    __nv_bfloat162 h23; h23.x = h[2]; h23.y = h[3];
    __nv_bfloat162 l01; l01.x = l[0]; l01.y = l[1];
    __nv_bfloat162 l23; l23.x = l[2]; l23.y = l[3];
    reinterpret_cast<__nv_bfloat162*>(hi)[2*i]   = h01;
    reinterpret_cast<__nv_bfloat162*>(hi)[2*i+1] = h23;
    reinterpret_cast<__nv_bfloat162*>(lo)[2*i]   = l01;
    reinterpret_cast<__nv_bfloat162*>(lo)[2*i+1] = l23;
}

// ---------------- bf16 transpose per batch: in [NSEQ, EDIM] -> out [EDIM, NSEQ] ---
__global__ __launch_bounds__(256)
void transpose_k(const bf16* __restrict__ in, bf16* __restrict__ out)
{
    __shared__ bf16 t[64][72];
    const int z = blockIdx.z;
    in  += (size_t)z * NSEQ * EDIM;
    out += (size_t)z * EDIM * NSEQ;
    const int x0 = blockIdx.x * 64;   // E tile
    const int y0 = blockIdx.y * 64;   // seq tile
    const int tid = threadIdx.x;
    const int r = tid >> 3, c = (tid & 7) * 8;
#pragma unroll
    for (int i = 0; i < 2; i++) {
        uint4 v = *(const uint4*)(in + (size_t)(y0 + r + 32*i) * EDIM + x0 + c);
        *(uint4*)&t[r + 32*i][c] = v;
    }
    __syncthreads();
#pragma unroll
    for (int i = 0; i < 2; i++) {
        int orow = r + 32*i;
        bf16 tmp[8];
#pragma unroll
        for (int j = 0; j < 8; j++) tmp[j] = t[c + j][orow];
        *(uint4*)(out + (size_t)(x0 + orow) * NSEQ + y0 + c) = *(uint4*)tmp;
    }
}

// ---------------- HMMA split-bf16 GEMM: C[M,N] = (Ah+Al) @ (Bh+Bl)^T ----------
// A: [M,K] row-major. B: [N,K] row-major (both K contiguous).
// CTA tile 128x128, K_TILE=32, 4-stage cp.async pipeline, 8 warps (64x32 each).
// OUT_MODE: 0 = fp32 out; 1 = split hi/lo bf16 out; 2 = fp32 out + bias.

#define KT       32
#define NSTAGE   4
#define MAT_B    (128 * 80)                 // one matrix per stage: 128 rows x 80 bytes
#define STAGE_B  (4 * MAT_B)                // Ah, Al, Bh, Bl
#define SMEM_B   (NSTAGE * STAGE_B)         // 163840

template<int OUT_MODE>
__global__ __launch_bounds__(256, 1)
void gemm_hmma(const bf16* __restrict__ Ah, const bf16* __restrict__ Al,
               const bf16* __restrict__ Bh, const bf16* __restrict__ Bl,
               float* __restrict__ outF, bf16* __restrict__ outHi, bf16* __restrict__ outLo,
               const float* __restrict__ bias,
               int M, int N, int K, long long sA, long long sB, long long sC)
{
    extern __shared__ __align__(16) char dsm[];
    const uint32_t sb = smem_u32(dsm);

    const int z = blockIdx.z;
    Ah += (size_t)z * sA;  Al += (size_t)z * sA;
    Bh += (size_t)z * sB;  Bl += (size_t)z * sB;

    const int tid = threadIdx.x;
    const int lane = tid & 31;
    const int warp = tid >> 5;
    const int m0 = blockIdx.y * 128;
    const int n0 = blockIdx.x * 128;

    const int wm0 = (warp & 1) * 64;
    const int wn0 = (warp >> 1) * 32;
    const int arow = lane & 15;
    const int acol = (lane >> 4) * 8;
    const int brow = lane & 7;
    const int bcol = ((lane >> 3) & 1) * 8;

    const int nk = K >> 5;

    // loader: each thread moves 2x16B per matrix per stage
    const int lrow0 = tid >> 2,           lc0 = (tid & 3);
    const int lrow1 = (tid + 256) >> 2,   lc1 = ((tid + 256) & 3);

    auto load_stage = [&](int kt, int stg) {
        const uint32_t base = sb + stg * STAGE_B;
        const int kk = kt << 5;
        {
            uint32_t d = base + lrow0 * 80 + lc0 * 16;
            const size_t go = (size_t)(m0 + lrow0) * K + kk + lc0 * 8;
            const size_t gb = (size_t)(n0 + lrow0) * K + kk + lc0 * 8;
            cpa16(d,             Ah + go);
            cpa16(d + MAT_B,     Al + go);
            cpa16(d + 2*MAT_B,   Bh + gb);
            cpa16(d + 3*MAT_B,   Bl + gb);
        }
        {
            uint32_t d = base + lrow1 * 80 + lc1 * 16;
            const size_t go = (size_t)(m0 + lrow1) * K + kk + lc1 * 8;
            const size_t gb = (size_t)(n0 + lrow1) * K + kk + lc1 * 8;
            cpa16(d,             Ah + go);
            cpa16(d + MAT_B,     Al + go);
            cpa16(d + 2*MAT_B,   Bh + gb);
            cpa16(d + 3*MAT_B,   Bl + gb);
        }
        asm volatile("cp.async.commit_group;" ::: "memory");
    };

    float acc[4][4][4];
#pragma unroll
    for (int t = 0; t < 4; t++)
#pragma unroll
        for (int u = 0; u < 4; u++)
#pragma unroll
            for (int e = 0; e < 4; e++) acc[t][u][e] = 0.0f;

    // prologue: 3 stages in flight
    load_stage(0, 0);
    load_stage(1, 1);
    load_stage(2, 2);

    for (int kt = 0; kt < nk; kt++) {
        asm volatile("cp.async.wait_group 2;" ::: "memory");
        __syncthreads();

        if (kt + 3 < nk) load_stage(kt + 3, (kt + 3) & (NSTAGE - 1));
        else             asm volatile("cp.async.commit_group;" ::: "memory");

        const uint32_t base = sb + (kt & (NSTAGE - 1)) * STAGE_B;

#pragma unroll
        for (int ks = 0; ks < 2; ks++) {
            const int kbyte = (ks * 16 + 0) * 2;
            uint32_t ah[4][4], al[4][4], bh[4][2], bl[4][2];
#pragma unroll
            for (int t = 0; t < 4; t++) {
                uint32_t ad = base + (uint32_t)(wm0 + t*16 + arow) * 80 + kbyte + acol * 2;
                asm volatile("ldmatrix.sync.aligned.m8n8.x4.shared.b16 {%0,%1,%2,%3}, [%4];\n"
                             : "=r"(ah[t][0]), "=r"(ah[t][1]), "=r"(ah[t][2]), "=r"(ah[t][3]) : "r"(ad));
                asm volatile("ldmatrix.sync.aligned.m8n8.x4.shared.b16 {%0,%1,%2,%3}, [%4];\n"
                             : "=r"(al[t][0]), "=r"(al[t][1]), "=r"(al[t][2]), "=r"(al[t][3]) : "r"(ad + MAT_B));
            }
#pragma unroll
            for (int u = 0; u < 4; u++) {
                uint32_t bd = base + 2*MAT_B + (uint32_t)(wn0 + u*8 + brow) * 80 + kbyte + bcol * 2;
                asm volatile("ldmatrix.sync.aligned.m8n8.x2.shared.b16 {%0,%1}, [%2];\n"
                             : "=r"(bh[u][0]), "=r"(bh[u][1]) : "r"(bd));
                asm volatile("ldmatrix.sync.aligned.m8n8.x2.shared.b16 {%0,%1}, [%2];\n"
                             : "=r"(bl[u][0]), "=r"(bl[u][1]) : "r"(bd + MAT_B));
            }
            // term-outermost: 16 independent accumulators between reuses of the same acc
#pragma unroll
            for (int t = 0; t < 4; t++)
#pragma unroll
                for (int u = 0; u < 4; u++) MMA_BF16(acc[t][u], ah[t], bh[u]);
#pragma unroll
            for (int t = 0; t < 4; t++)
#pragma unroll
                for (int u = 0; u < 4; u++) MMA_BF16(acc[t][u], ah[t], bl[u]);
#pragma unroll
            for (int t = 0; t < 4; t++)
#pragma unroll
                for (int u = 0; u < 4; u++) MMA_BF16(acc[t][u], al[t], bh[u]);
        }
    }

    // ---- epilogue ----
    const size_t cbase = (size_t)z * sC;
#pragma unroll
    for (int t = 0; t < 4; t++)
#pragma unroll
        for (int u = 0; u < 4; u++) {
            int gm = m0 + wm0 + t * 16 + (lane >> 2);
            int gn = n0 + wn0 + u * 8 + (lane & 3) * 2;
            float v00 = acc[t][u][0], v01 = acc[t][u][1];
            float v10 = acc[t][u][2], v11 = acc[t][u][3];
            if (OUT_MODE == 2) {
                float b0 = bias[gn], b1 = bias[gn + 1];
                v00 += b0; v01 += b1; v10 += b0; v11 += b1;
            }
            if (OUT_MODE == 0 || OUT_MODE == 2) {
                *(float2*)(outF + cbase + (size_t)gm * N + gn) = make_float2(v00, v01);
                *(float2*)(outF + cbase + (size_t)(gm + 8) * N + gn) = make_float2(v10, v11);
            } else {
                bf16 h00 = __float2bfloat16(v00), h01 = __float2bfloat16(v01);
                bf16 h10 = __float2bfloat16(v10), h11 = __float2bfloat16(v11);
                __nv_bfloat162 hp0; hp0.x = h00; hp0.y = h01;
                __nv_bfloat162 hp1; hp1.x = h10; hp1.y = h11;
                __nv_bfloat162 lp0; lp0.x = __float2bfloat16(v00 - __bfloat162float(h00));
                                    lp0.y = __float2bfloat16(v01 - __bfloat162float(h01));
                __nv_bfloat162 lp1; lp1.x = __float2bfloat16(v10 - __bfloat162float(h10));
                                    lp1.y = __float2bfloat16(v11 - __bfloat162float(h11));
                *(__nv_bfloat162*)(outHi + cbase + (size_t)gm * N + gn) = hp0;
                *(__nv_bfloat162*)(outHi + cbase + (size_t)(gm + 8) * N + gn) = hp1;
                *(__nv_bfloat162*)(outLo + cbase + (size_t)gm * N + gn) = lp0;
                *(__nv_bfloat162*)(outLo + cbase + (size_t)(gm + 8) * N + gn) = lp1;
            }
        }
}

// ---------------- row softmax (scaled) with split-bf16 output ----------------
__global__ __launch_bounds__(256)
void softmax_split(const float* __restrict__ S, bf16* __restrict__ Ph, bf16* __restrict__ Pl,
                   float scale)
{
    __shared__ float buf[NSEQ];
    __shared__ float red[8];
    const size_t base = (size_t)blockIdx.x * NSEQ;
    const int tid = threadIdx.x;

    float lmax = -1e30f;
#pragma unroll
    for (int i = 0; i < NSEQ / (256 * 4); i++) {
        int idx = (i * 256 + tid) * 4;
        float4 v = *(const float4*)(S + base + idx);
        buf[idx] = v.x; buf[idx + 1] = v.y; buf[idx + 2] = v.z; buf[idx + 3] = v.w;
        lmax = fmaxf(lmax, fmaxf(fmaxf(v.x, v.y), fmaxf(v.z, v.w)));
    }
#pragma unroll
    for (int o = 16; o; o >>= 1) lmax = fmaxf(lmax, __shfl_xor_sync(0xffffffffu, lmax, o));
    if ((tid & 31) == 0) red[tid >> 5] = lmax;
    __syncthreads();
    float rmax = red[0];
#pragma unroll
    for (int j = 1; j < 8; j++) rmax = fmaxf(rmax, red[j]);
    __syncthreads();

    float lsum = 0.0f;
#pragma unroll
    for (int i = 0; i < NSEQ / (256 * 4); i++) {
        int idx = (i * 256 + tid) * 4;
#pragma unroll
        for (int j = 0; j < 4; j++) {
            float e = expf(scale * (buf[idx + j] - rmax));
            buf[idx + j] = e;
            lsum += e;
        }
    }
#pragma unroll
    for (int o = 16; o; o >>= 1) lsum += __shfl_xor_sync(0xffffffffu, lsum, o);
    if ((tid & 31) == 0) red[tid >> 5] = lsum;
    __syncthreads();
    float rsum = red[0];
#pragma unroll
    for (int j = 1; j < 8; j++) rsum += red[j];
    float rinv = 1.0f / rsum;

#pragma unroll
    for (int i = 0; i < NSEQ / (256 * 4); i++) {
        int idx = (i * 256 + tid) * 4;
        bf16 h[4], l[4];
#pragma unroll
        for (int j = 0; j < 4; j++) {
            float p = buf[idx + j] * rinv;
            h[j] = __float2bfloat16(p);
            l[j] = __float2bfloat16(p - __bfloat162float(h[j]));
        }
        __nv_bfloat162 h01; h01.x = h[0]; h01.y = h[1];
        __nv_bfloat162 h23; h23.x = h[2]; h23.y = h[3];
        __nv_bfloat162 l01; l01.x = l[0]; l01.y = l[1];
        __nv_bfloat162 l23; l23.x = l[2]; l23.y = l[3];
        *(__nv_bfloat162*)(Ph + base + idx)     = h01;
        *(__nv_bfloat162*)(Ph + base + idx + 2) = h23;
        *(__nv_bfloat162*)(Pl + base + idx)     = l01;
        *(__nv_bfloat162*)(Pl + base + idx + 2) = l23;
    }
}

// ---------------- host ----------------
extern "C" void kernel_launch(void* const* d_in, const int* in_sizes, int n_in,
                              void* d_out, int out_size)
{
    const float* x  = (const float*)d_in[0];
    const float* y  = (const float*)d_in[1];
    const float* Wq = (const float*)d_in[2];
    const float* Wk = (const float*)d_in[3];
    const float* Wv = (const float*)d_in[4];
    const float* Wo = (const float*)d_in[5];
    const float* bo = (const float*)d_in[6];
    float* out = (float*)d_out;

    void *xh, *xl, *yh, *yl;
    void *wqh, *wql, *wkh, *wkl, *wvh, *wvl, *woh, *wol;
    void *qh, *ql, *kh, *kl, *vh, *vl, *vth, *vtl, *sS, *ph, *pl, *ch, *cl;
    cudaGetSymbolAddress(&xh, g_xh);   cudaGetSymbolAddress(&xl, g_xl);
    cudaGetSymbolAddress(&yh, g_yh);   cudaGetSymbolAddress(&yl, g_yl);
    cudaGetSymbolAddress(&wqh, g_wqh); cudaGetSymbolAddress(&wql, g_wql);
    cudaGetSymbolAddress(&wkh, g_wkh); cudaGetSymbolAddress(&wkl, g_wkl);
    cudaGetSymbolAddress(&wvh, g_wvh); cudaGetSymbolAddress(&wvl, g_wvl);
    cudaGetSymbolAddress(&woh, g_woh); cudaGetSymbolAddress(&wol, g_wol);
    cudaGetSymbolAddress(&qh, g_qh);   cudaGetSymbolAddress(&ql, g_ql);
    cudaGetSymbolAddress(&kh, g_kh);   cudaGetSymbolAddress(&kl, g_kl);
    cudaGetSymbolAddress(&vh, g_vh);   cudaGetSymbolAddress(&vl, g_vl);
    cudaGetSymbolAddress(&vth, g_vth); cudaGetSymbolAddress(&vtl, g_vtl);
    cudaGetSymbolAddress(&sS, g_S);
    cudaGetSymbolAddress(&ph, g_ph);   cudaGetSymbolAddress(&pl, g_pl);
    cudaGetSymbolAddress(&ch, g_ch);   cudaGetSymbolAddress(&cl, g_cl);

    cudaFuncSetAttribute(gemm_hmma<0>, cudaFuncAttributeMaxDynamicSharedMemorySize, SMEM_B);
    cudaFuncSetAttribute(gemm_hmma<1>, cudaFuncAttributeMaxDynamicSharedMemorySize, SMEM_B);
    cudaFuncSetAttribute(gemm_hmma<2>, cudaFuncAttributeMaxDynamicSharedMemorySize, SMEM_B);

    const int MBN = BATCH * NSEQ;            // 16384

    // 1) splits
    {
        int n4 = BATCH * NSEQ * DDIM / 4;
        split_kernel<<<n4 / 256, 256>>>((const float4*)x, (bf16*)xh, (bf16*)xl, n4);
        split_kernel<<<n4 / 256, 256>>>((const float4*)y, (bf16*)yh, (bf16*)yl, n4);
        int w4 = EDIM * DDIM / 4;
        split_kernel<<<w4 / 256, 256>>>((const float4*)Wq, (bf16*)wqh, (bf16*)wql, w4);
        split_kernel<<<w4 / 256, 256>>>((const float4*)Wk, (bf16*)wkh, (bf16*)wkl, w4);
        split_kernel<<<w4 / 256, 256>>>((const float4*)Wv, (bf16*)wvh, (bf16*)wvl, w4);
        split_kernel<<<w4 / 256, 256>>>((const float4*)Wo, (bf16*)woh, (bf16*)wol, w4);
    }

    // 2) projections: q = y @ Wq^T, k = x @ Wk^T, v = x @ Wv^T (M=16384, N=1024, K=1024)
    {
        dim3 grid(EDIM / 128, MBN / 128, 1);
        gemm_hmma<1><<<grid, 256, SMEM_B>>>((bf16*)yh, (bf16*)yl, (bf16*)wqh, (bf16*)wql,
                                            nullptr, (bf16*)qh, (bf16*)ql, nullptr,
                                            MBN, EDIM, DDIM, 0, 0, 0);
        gemm_hmma<1><<<grid, 256, SMEM_B>>>((bf16*)xh, (bf16*)xl, (bf16*)wkh, (bf16*)wkl,
                                            nullptr, (bf16*)kh, (bf16*)kl, nullptr,
                                            MBN, EDIM, DDIM, 0, 0, 0);
        gemm_hmma<1><<<grid, 256, SMEM_B>>>((bf16*)xh, (bf16*)xl, (bf16*)wvh, (bf16*)wvl,
                                            nullptr, (bf16*)vh, (bf16*)vl, nullptr,
                                            MBN, EDIM, DDIM, 0, 0, 0);
    }

    // 3) scores: S[b] = q[b] @ k[b]^T   (M=N=4096, K=1024)
    {
        dim3 grid(NSEQ / 128, NSEQ / 128, BATCH);
        gemm_hmma<0><<<grid, 256, SMEM_B>>>((bf16*)qh, (bf16*)ql, (bf16*)kh, (bf16*)kl,
                                            (float*)sS, nullptr, nullptr, nullptr,
                                            NSEQ, NSEQ, EDIM,
                                            (long long)NSEQ * EDIM, (long long)NSEQ * EDIM,
                                            (long long)NSEQ * NSEQ);
    }

    // 4) softmax (scale = 1/32), split-bf16 P
    softmax_split<<<BATCH * NSEQ, 256>>>((const float*)sS, (bf16*)ph, (bf16*)pl, 1.0f / 32.0f);

    // 4b) transpose V -> V^T [EDIM, NSEQ] per batch (so PV uses K-contiguous B)
    {
        dim3 grid(EDIM / 64, NSEQ / 64, BATCH);
        transpose_k<<<grid, 256>>>((bf16*)vh, (bf16*)vth);
        transpose_k<<<grid, 256>>>((bf16*)vl, (bf16*)vtl);
    }

    // 5) ctx: C[b] = P[b] @ (V^T[b])^T  (M=4096, N=1024, K=4096)
    {
        dim3 grid(EDIM / 128, NSEQ / 128, BATCH);
        gemm_hmma<1><<<grid, 256, SMEM_B>>>((bf16*)ph, (bf16*)pl, (bf16*)vth, (bf16*)vtl,
                                            nullptr, (bf16*)ch, (bf16*)cl, nullptr,
                                            NSEQ, EDIM, NSEQ,
                                            (long long)NSEQ * NSEQ, (long long)EDIM * NSEQ,
                                            (long long)NSEQ * EDIM);
    }

    // 6) out = ctx @ Wo^T + bo   (M=16384, N=1024, K=1024)
    {
        dim3 grid(DDIM / 128, MBN / 128, 1);
        gemm_hmma<2><<<grid, 256, SMEM_B>>>((bf16*)ch, (bf16*)cl, (bf16*)woh, (bf16*)wol,
                                            out, nullptr, nullptr, bo,
                                            MBN, DDIM, EDIM, 0, 0, 0);
    }

    (void)in_sizes; (void)n_in; (void)out_size;
}

// round 4
// speedup vs baseline: 1.4257x; 1.0169x over previous
#include <cuda_runtime.h>
#include <cuda_bf16.h>
#include <stdint.h>

#define BATCH 4
#define NSEQ  4096
#define DDIM  1024
#define EDIM  1024

typedef __nv_bfloat16 bf16;

// ---------------- scratch (device globals; no allocations allowed) -------------
__device__ bf16 g_xh[(size_t)BATCH*NSEQ*DDIM], g_xl[(size_t)BATCH*NSEQ*DDIM];
__device__ bf16 g_yh[(size_t)BATCH*NSEQ*DDIM], g_yl[(size_t)BATCH*NSEQ*DDIM];
__device__ bf16 g_wqh[(size_t)EDIM*DDIM], g_wql[(size_t)EDIM*DDIM];
__device__ bf16 g_wkh[(size_t)EDIM*DDIM], g_wkl[(size_t)EDIM*DDIM];
__device__ bf16 g_wvh[(size_t)EDIM*DDIM], g_wvl[(size_t)EDIM*DDIM];
__device__ bf16 g_woh[(size_t)DDIM*EDIM], g_wol[(size_t)DDIM*EDIM];
__device__ bf16 g_qh[(size_t)BATCH*NSEQ*EDIM], g_ql[(size_t)BATCH*NSEQ*EDIM];
__device__ bf16 g_kh[(size_t)BATCH*NSEQ*EDIM], g_kl[(size_t)BATCH*NSEQ*EDIM];
__device__ bf16 g_vh[(size_t)BATCH*NSEQ*EDIM], g_vl[(size_t)BATCH*NSEQ*EDIM];
__device__ bf16 g_vth[(size_t)BATCH*EDIM*NSEQ], g_vtl[(size_t)BATCH*EDIM*NSEQ];
__device__ float g_S[(size_t)BATCH*NSEQ*NSEQ];
__device__ bf16 g_ph[(size_t)BATCH*NSEQ*NSEQ], g_pl[(size_t)BATCH*NSEQ*NSEQ];
__device__ bf16 g_ch[(size_t)BATCH*NSEQ*EDIM], g_cl[(size_t)BATCH*NSEQ*EDIM];

// ---------------- helpers ----------------
__device__ __forceinline__ uint32_t smem_u32(const void* p) {
    uint32_t a;
    asm("{ .reg .u64 t; cvta.to.shared.u64 t, %1; cvt.u32.u64 %0, t; }" : "=r"(a) : "l"(p));
    return a;
}
__device__ __forceinline__ void cpa16(uint32_t dst, const void* src) {
    asm volatile("cp.async.cg.shared.global [%0], [%1], 16;" :: "r"(dst), "l"(src));
}

#define MMA_BF16(c, a, b) \
    asm volatile("mma.sync.aligned.m16n8k16.row.col.f32.bf16.bf16.f32 " \
                 "{%0,%1,%2,%3},{%4,%5,%6,%7},{%8,%9},{%0,%1,%2,%3};\n" \
                 : "+f"(c[0]), "+f"(c[1]), "+f"(c[2]), "+f"(c[3]) \
                 : "r"(a[0]), "r"(a[1]), "r"(a[2]), "r"(a[3]), "r"(b[0]), "r"(b[1]))

// ---------------- fp32 -> bf16 hi/lo split ----------------
__global__ void split_kernel(const float4* __restrict__ src,
                             bf16* __restrict__ hi, bf16* __restrict__ lo, int n4)
{
    int i = blockIdx.x * blockDim.x + threadIdx.x;
    if (i >= n4) return;
    float4 v = src[i];
    float vs[4] = {v.x, v.y, v.z, v.w};
    bf16 h[4], l[4];
#pragma unroll
    for (int j = 0; j < 4; j++) {
        h[j] = __float2bfloat16(vs[j]);
        l[j] = __float2bfloat16(vs[j] - __bfloat162float(h[j]));
    }
    __nv_bfloat162 h01; h01.x = h[0]; h01.y = h[1];
    __nv_bfloat162 h23; h23.x = h[2]; h23.y = h[3];
    __nv_bfloat162 l01; l01.x = l[0]; l01.y = l[1];
    __nv_bfloat162 l23; l23.x = l[2]; l23.y = l[3];
    reinterpret_cast<__nv_bfloat162*>(hi)[2*i]   = h01;
    reinterpret_cast<__nv_bfloat162*>(hi)[2*i+1] = h23;
    reinterpret_cast<__nv_bfloat162*>(lo)[2*i]   = l01;
    reinterpret_cast<__nv_bfloat162*>(lo)[2*i+1] = l23;
}

// ---------------- bf16 transpose per batch: in [NSEQ, EDIM] -> out [EDIM, NSEQ] ---
__global__ __launch_bounds__(256)
void transpose_k(const bf16* __restrict__ in, bf16* __restrict__ out)
{
    __shared__ bf16 t[64][72];
    const int z = blockIdx.z;
    in  += (size_t)z * NSEQ * EDIM;
    out += (size_t)z * EDIM * NSEQ;
    const int x0 = blockIdx.x * 64;   // E tile
    const int y0 = blockIdx.y * 64;   // seq tile
    const int tid = threadIdx.x;
    const int r = tid >> 3, c = (tid & 7) * 8;
#pragma unroll
    for (int i = 0; i < 2; i++) {
        uint4 v = *(const uint4*)(in + (size_t)(y0 + r + 32*i) * EDIM + x0 + c);
        *(uint4*)&t[r + 32*i][c] = v;
    }
    __syncthreads();
#pragma unroll
    for (int i = 0; i < 2; i++) {
        int orow = r + 32*i;
        bf16 tmp[8];
#pragma unroll
        for (int j = 0; j < 8; j++) tmp[j] = t[c + j][orow];
        *(uint4*)(out + (size_t)(x0 + orow) * NSEQ + y0 + c) = *(uint4*)tmp;
    }
}

// ---------------- HMMA split-bf16 GEMM: C[M,N] = (Ah+Al) @ (Bh+Bl)^T ----------
// A: [M,K] row-major. B: [N,K] row-major (both K contiguous).
// CTA tile 128 (M) x 256 (N), K_TILE=32, 3-stage cp.async pipeline.
// 8 warps, each 64x64. OUT_MODE: 0 fp32; 1 split hi/lo bf16; 2 fp32 + bias.

#define NSTAGE   3
#define MAT_A    (128 * 80)
#define MAT_BB   (256 * 80)
#define OFF_AL   (MAT_A)
#define OFF_BH   (2 * MAT_A)
#define OFF_BL   (2 * MAT_A + MAT_BB)
#define STAGE_B  (2 * MAT_A + 2 * MAT_BB)      // 61440
#define SMEM_B   (NSTAGE * STAGE_B)            // 184320

template<int OUT_MODE>
__global__ __launch_bounds__(256, 1)
void gemm_hmma(const bf16* __restrict__ Ah, const bf16* __restrict__ Al,
               const bf16* __restrict__ Bh, const bf16* __restrict__ Bl,
               float* __restrict__ outF, bf16* __restrict__ outHi, bf16* __restrict__ outLo,
               const float* __restrict__ bias,
               int M, int N, int K, long long sA, long long sB, long long sC)
{
    extern __shared__ __align__(16) char dsm[];
    const uint32_t sb = smem_u32(dsm);

    const int z = blockIdx.z;
    Ah += (size_t)z * sA;  Al += (size_t)z * sA;
    Bh += (size_t)z * sB;  Bl += (size_t)z * sB;

    const int tid = threadIdx.x;
    const int lane = tid & 31;
    const int warp = tid >> 5;
    const int m0 = blockIdx.y * 128;
    const int n0 = blockIdx.x * 256;

    const int wm0 = (warp & 1) * 64;          // 2 warps along M
    const int wn0 = (warp >> 1) * 64;         // 4 warps along N
    const int arow = lane & 15;
    const int acol = (lane >> 4) * 8;
    const int brow = lane & 7;
    const int bcol = ((lane >> 3) & 1) * 8;

    const int nk = K >> 5;

    // loader: A chunks (512 of 16B per matrix-pair half) + B chunks (1024)
    const int ar0 = tid >> 2,          ac0 = (tid & 3);
    const int ar1 = (tid + 256) >> 2,  ac1 = ((tid + 256) & 3);

    auto load_stage = [&](int kt, int stg) {
        const uint32_t base = sb + stg * STAGE_B;
        const int kk = kt << 5;
        // A: 128 rows x 4 chunks, hi+lo
        {
            uint32_t d = base + ar0 * 80 + ac0 * 16;
            const size_t g = (size_t)(m0 + ar0) * K + kk + ac0 * 8;
            cpa16(d,          Ah + g);
            cpa16(d + OFF_AL, Al + g);
        }
        {
            uint32_t d = base + ar1 * 80 + ac1 * 16;
            const size_t g = (size_t)(m0 + ar1) * K + kk + ac1 * 8;
            cpa16(d,          Ah + g);
            cpa16(d + OFF_AL, Al + g);
        }
        // B: 256 rows x 4 chunks, hi+lo
#pragma unroll
        for (int i = 0; i < 4; i++) {
            const int idx = tid + 256 * i;
            const int br = idx >> 2, bc = idx & 3;
            uint32_t d = base + OFF_BH + br * 80 + bc * 16;
            const size_t g = (size_t)(n0 + br) * K + kk + bc * 8;
            cpa16(d,                   Bh + g);
            cpa16(d + (OFF_BL-OFF_BH), Bl + g);
        }
        asm volatile("cp.async.commit_group;" ::: "memory");
    };

    float acc[4][8][4];
#pragma unroll
    for (int t = 0; t < 4; t++)
#pragma unroll
        for (int u = 0; u < 8; u++)
#pragma unroll
            for (int e = 0; e < 4; e++) acc[t][u][e] = 0.0f;

    load_stage(0, 0);
    load_stage(1, 1);

    for (int kt = 0; kt < nk; kt++) {
        asm volatile("cp.async.wait_group 1;" ::: "memory");
        __syncthreads();

        if (kt + 2 < nk) load_stage(kt + 2, (kt + 2) % NSTAGE);
        else             asm volatile("cp.async.commit_group;" ::: "memory");

        const uint32_t base = sb + (kt % NSTAGE) * STAGE_B;

#pragma unroll
        for (int ks = 0; ks < 2; ks++) {
            const int kbyte = ks * 32;
            uint32_t ah[4][4], al[4][4], bh[8][2], bl[8][2];
#pragma unroll
            for (int t = 0; t < 4; t++) {
                uint32_t ad = base + (uint32_t)(wm0 + t*16 + arow) * 80 + kbyte + acol * 2;
                asm volatile("ldmatrix.sync.aligned.m8n8.x4.shared.b16 {%0,%1,%2,%3}, [%4];\n"
                             : "=r"(ah[t][0]), "=r"(ah[t][1]), "=r"(ah[t][2]), "=r"(ah[t][3]) : "r"(ad));
                asm volatile("ldmatrix.sync.aligned.m8n8.x4.shared.b16 {%0,%1,%2,%3}, [%4];\n"
                             : "=r"(al[t][0]), "=r"(al[t][1]), "=r"(al[t][2]), "=r"(al[t][3]) : "r"(ad + OFF_AL));
            }
#pragma unroll
            for (int u = 0; u < 8; u++) {
                uint32_t bd = base + OFF_BH + (uint32_t)(wn0 + u*8 + brow) * 80 + kbyte + bcol * 2;
                asm volatile("ldmatrix.sync.aligned.m8n8.x2.shared.b16 {%0,%1}, [%2];\n"
                             : "=r"(bh[u][0]), "=r"(bh[u][1]) : "r"(bd));
                asm volatile("ldmatrix.sync.aligned.m8n8.x2.shared.b16 {%0,%1}, [%2];\n"
                             : "=r"(bl[u][0]), "=r"(bl[u][1]) : "r"(bd + (OFF_BL-OFF_BH)));
            }
            // term-outermost: 32 independent accumulators between reuses
#pragma unroll
            for (int t = 0; t < 4; t++)
#pragma unroll
                for (int u = 0; u < 8; u++) MMA_BF16(acc[t][u], ah[t], bh[u]);
#pragma unroll
            for (int t = 0; t < 4; t++)
#pragma unroll
                for (int u = 0; u < 8; u++) MMA_BF16(acc[t][u], ah[t], bl[u]);
#pragma unroll
            for (int t = 0; t < 4; t++)
#pragma unroll
                for (int u = 0; u < 8; u++) MMA_BF16(acc[t][u], al[t], bh[u]);
        }
    }

    // ---- epilogue ----
    const size_t cbase = (size_t)z * sC;
#pragma unroll
    for (int t = 0; t < 4; t++)
#pragma unroll
        for (int u = 0; u < 8; u++) {
            int gm = m0 + wm0 + t * 16 + (lane >> 2);
            int gn = n0 + wn0 + u * 8 + (lane & 3) * 2;
            float v00 = acc[t][u][0], v01 = acc[t][u][1];
            float v10 = acc[t][u][2], v11 = acc[t][u][3];
            if (OUT_MODE == 2) {
                float b0 = bias[gn], b1 = bias[gn + 1];
                v00 += b0; v01 += b1; v10 += b0; v11 += b1;
            }
            if (OUT_MODE == 0 || OUT_MODE == 2) {
                *(float2*)(outF + cbase + (size_t)gm * N + gn) = make_float2(v00, v01);
                *(float2*)(outF + cbase + (size_t)(gm + 8) * N + gn) = make_float2(v10, v11);
            } else {
                bf16 h00 = __float2bfloat16(v00), h01 = __float2bfloat16(v01);
                bf16 h10 = __float2bfloat16(v10), h11 = __float2bfloat16(v11);
                __nv_bfloat162 hp0; hp0.x = h00; hp0.y = h01;
                __nv_bfloat162 hp1; hp1.x = h10; hp1.y = h11;
                __nv_bfloat162 lp0; lp0.x = __float2bfloat16(v00 - __bfloat162float(h00));
                                    lp0.y = __float2bfloat16(v01 - __bfloat162float(h01));
                __nv_bfloat162 lp1; lp1.x = __float2bfloat16(v10 - __bfloat162float(h10));
                                    lp1.y = __float2bfloat16(v11 - __bfloat162float(h11));
                *(__nv_bfloat162*)(outHi + cbase + (size_t)gm * N + gn) = hp0;
                *(__nv_bfloat162*)(outHi + cbase + (size_t)(gm + 8) * N + gn) = hp1;
                *(__nv_bfloat162*)(outLo + cbase + (size_t)gm * N + gn) = lp0;
                *(__nv_bfloat162*)(outLo + cbase + (size_t)(gm + 8) * N + gn) = lp1;
            }
        }
}

// ---------------- row softmax (scaled) with split-bf16 output ----------------
__global__ __launch_bounds__(256)
void softmax_split(const float* __restrict__ S, bf16* __restrict__ Ph, bf16* __restrict__ Pl,
                   float scale)
{
    __shared__ float buf[NSEQ];
    __shared__ float red[8];
    const size_t base = (size_t)blockIdx.x * NSEQ;
    const int tid = threadIdx.x;

    float lmax = -1e30f;
#pragma unroll
    for (int i = 0; i < NSEQ / (256 * 4); i++) {
        int idx = (i * 256 + tid) * 4;
        float4 v = *(const float4*)(S + base + idx);
        buf[idx] = v.x; buf[idx + 1] = v.y; buf[idx + 2] = v.z; buf[idx + 3] = v.w;
        lmax = fmaxf(lmax, fmaxf(fmaxf(v.x, v.y), fmaxf(v.z, v.w)));
    }
#pragma unroll
    for (int o = 16; o; o >>= 1) lmax = fmaxf(lmax, __shfl_xor_sync(0xffffffffu, lmax, o));
    if ((tid & 31) == 0) red[tid >> 5] = lmax;
    __syncthreads();
    float rmax = red[0];
#pragma unroll
    for (int j = 1; j < 8; j++) rmax = fmaxf(rmax, red[j]);
    __syncthreads();

    float lsum = 0.0f;
#pragma unroll
    for (int i = 0; i < NSEQ / (256 * 4); i++) {
        int idx = (i * 256 + tid) * 4;
#pragma unroll
        for (int j = 0; j < 4; j++) {
            float e = expf(scale * (buf[idx + j] - rmax));
            buf[idx + j] = e;
            lsum += e;
        }
    }
#pragma unroll
    for (int o = 16; o; o >>= 1) lsum += __shfl_xor_sync(0xffffffffu, lsum, o);
    if ((tid & 31) == 0) red[tid >> 5] = lsum;
    __syncthreads();
    float rsum = red[0];
#pragma unroll
    for (int j = 1; j < 8; j++) rsum += red[j];
    float rinv = 1.0f / rsum;

#pragma unroll
    for (int i = 0; i < NSEQ / (256 * 4); i++) {
        int idx = (i * 256 + tid) * 4;
        bf16 h[4], l[4];
#pragma unroll
        for (int j = 0; j < 4; j++) {
            float p = buf[idx + j] * rinv;
            h[j] = __float2bfloat16(p);
            l[j] = __float2bfloat16(p - __bfloat162float(h[j]));
        }
        __nv_bfloat162 h01; h01.x = h[0]; h01.y = h[1];
        __nv_bfloat162 h23; h23.x = h[2]; h23.y = h[3];
        __nv_bfloat162 l01; l01.x = l[0]; l01.y = l[1];
        __nv_bfloat162 l23; l23.x = l[2]; l23.y = l[3];
        *(__nv_bfloat162*)(Ph + base + idx)     = h01;
        *(__nv_bfloat162*)(Ph + base + idx + 2) = h23;
        *(__nv_bfloat162*)(Pl + base + idx)     = l01;
        *(__nv_bfloat162*)(Pl + base + idx + 2) = l23;
    }
}

// ---------------- host ----------------
extern "C" void kernel_launch(void* const* d_in, const int* in_sizes, int n_in,
                              void* d_out, int out_size)
{
    const float* x  = (const float*)d_in[0];
    const float* y  = (const float*)d_in[1];
    const float* Wq = (const float*)d_in[2];
    const float* Wk = (const float*)d_in[3];
    const float* Wv = (const float*)d_in[4];
    const float* Wo = (const float*)d_in[5];
    const float* bo = (const float*)d_in[6];
    float* out = (float*)d_out;

    void *xh, *xl, *yh, *yl;
    void *wqh, *wql, *wkh, *wkl, *wvh, *wvl, *woh, *wol;
    void *qh, *ql, *kh, *kl, *vh, *vl, *vth, *vtl, *sS, *ph, *pl, *ch, *cl;
    cudaGetSymbolAddress(&xh, g_xh);   cudaGetSymbolAddress(&xl, g_xl);
    cudaGetSymbolAddress(&yh, g_yh);   cudaGetSymbolAddress(&yl, g_yl);
    cudaGetSymbolAddress(&wqh, g_wqh); cudaGetSymbolAddress(&wql, g_wql);
    cudaGetSymbolAddress(&wkh, g_wkh); cudaGetSymbolAddress(&wkl, g_wkl);
    cudaGetSymbolAddress(&wvh, g_wvh); cudaGetSymbolAddress(&wvl, g_wvl);
    cudaGetSymbolAddress(&woh, g_woh); cudaGetSymbolAddress(&wol, g_wol);
    cudaGetSymbolAddress(&qh, g_qh);   cudaGetSymbolAddress(&ql, g_ql);
    cudaGetSymbolAddress(&kh, g_kh);   cudaGetSymbolAddress(&kl, g_kl);
    cudaGetSymbolAddress(&vh, g_vh);   cudaGetSymbolAddress(&vl, g_vl);
    cudaGetSymbolAddress(&vth, g_vth); cudaGetSymbolAddress(&vtl, g_vtl);
    cudaGetSymbolAddress(&sS, g_S);
    cudaGetSymbolAddress(&ph, g_ph);   cudaGetSymbolAddress(&pl, g_pl);
    cudaGetSymbolAddress(&ch, g_ch);   cudaGetSymbolAddress(&cl, g_cl);

    cudaFuncSetAttribute(gemm_hmma<0>, cudaFuncAttributeMaxDynamicSharedMemorySize, SMEM_B);
    cudaFuncSetAttribute(gemm_hmma<1>, cudaFuncAttributeMaxDynamicSharedMemorySize, SMEM_B);
    cudaFuncSetAttribute(gemm_hmma<2>, cudaFuncAttributeMaxDynamicSharedMemorySize, SMEM_B);

    const int MBN = BATCH * NSEQ;            // 16384

    // 1) splits
    {
        int n4 = BATCH * NSEQ * DDIM / 4;
        split_kernel<<<n4 / 256, 256>>>((const float4*)x, (bf16*)xh, (bf16*)xl, n4);
        split_kernel<<<n4 / 256, 256>>>((const float4*)y, (bf16*)yh, (bf16*)yl, n4);
        int w4 = EDIM * DDIM / 4;
        split_kernel<<<w4 / 256, 256>>>((const float4*)Wq, (bf16*)wqh, (bf16*)wql, w4);
        split_kernel<<<w4 / 256, 256>>>((const float4*)Wk, (bf16*)wkh, (bf16*)wkl, w4);
        split_kernel<<<w4 / 256, 256>>>((const float4*)Wv, (bf16*)wvh, (bf16*)wvl, w4);
        split_kernel<<<w4 / 256, 256>>>((const float4*)Wo, (bf16*)woh, (bf16*)wol, w4);
    }

    // 2) projections: q = y @ Wq^T, k = x @ Wk^T, v = x @ Wv^T (M=16384, N=1024, K=1024)
    {
        dim3 grid(EDIM / 256, MBN / 128, 1);
        gemm_hmma<1><<<grid, 256, SMEM_B>>>((bf16*)yh, (bf16*)yl, (bf16*)wqh, (bf16*)wql,
                                            nullptr, (bf16*)qh, (bf16*)ql, nullptr,
                                            MBN, EDIM, DDIM, 0, 0, 0);
        gemm_hmma<1><<<grid, 256, SMEM_B>>>((bf16*)xh, (bf16*)xl, (bf16*)wkh, (bf16*)wkl,
                                            nullptr, (bf16*)kh, (bf16*)kl, nullptr,
                                            MBN, EDIM, DDIM, 0, 0, 0);
        gemm_hmma<1><<<grid, 256, SMEM_B>>>((bf16*)xh, (bf16*)xl, (bf16*)wvh, (bf16*)wvl,
                                            nullptr, (bf16*)vh, (bf16*)vl, nullptr,
                                            MBN, EDIM, DDIM, 0, 0, 0);
    }

    // 3) scores: S[b] = q[b] @ k[b]^T   (M=N=4096, K=1024)
    {
        dim3 grid(NSEQ / 256, NSEQ / 128, BATCH);
        gemm_hmma<0><<<grid, 256, SMEM_B>>>((bf16*)qh, (bf16*)ql, (bf16*)kh, (bf16*)kl,
                                            (float*)sS, nullptr, nullptr, nullptr,
                                            NSEQ, NSEQ, EDIM,
                                            (long long)NSEQ * EDIM, (long long)NSEQ * EDIM,
                                            (long long)NSEQ * NSEQ);
    }

    // 4) softmax (scale = 1/32), split-bf16 P
    softmax_split<<<BATCH * NSEQ, 256>>>((const float*)sS, (bf16*)ph, (bf16*)pl, 1.0f / 32.0f);

    // 4b) transpose V -> V^T [EDIM, NSEQ] per batch (so PV uses K-contiguous B)
    {
        dim3 grid(EDIM / 64, NSEQ / 64, BATCH);
        transpose_k<<<grid, 256>>>((bf16*)vh, (bf16*)vth);
        transpose_k<<<grid, 256>>>((bf16*)vl, (bf16*)vtl);
    }

    // 5) ctx: C[b] = P[b] @ (V^T[b])^T  (M=4096, N=1024, K=4096)
    {
        dim3 grid(EDIM / 256, NSEQ / 128, BATCH);
        gemm_hmma<1><<<grid, 256, SMEM_B>>>((bf16*)ph, (bf16*)pl, (bf16*)vth, (bf16*)vtl,
                                            nullptr, (bf16*)ch, (bf16*)cl, nullptr,
                                            NSEQ, EDIM, NSEQ,
                                            (long long)NSEQ * NSEQ, (long long)EDIM * NSEQ,
                                            (long long)NSEQ * EDIM);
    }

    // 6) out = ctx @ Wo^T + bo   (M=16384, N=1024, K=1024)
    {
        dim3 grid(DDIM / 256, MBN / 128, 1);
        gemm_hmma<2><<<grid, 256, SMEM_B>>>((bf16*)ch, (bf16*)cl, (bf16*)woh, (bf16*)wol,
                                            out, nullptr, nullptr, bo,
                                            MBN, DDIM, EDIM, 0, 0, 0);
    }

    (void)in_sizes; (void)n_in; (void)out_size;
}